// round 5
// baseline (speedup 1.0000x reference)
#include <cuda_runtime.h>
#include <cuda_bf16.h>
#include <cub/cub.cuh>

#define CH 1024
#define SC 16
#define SCAP 1800
constexpr int MAXN = 1 << 18;
constexpr int MAXC = MAXN / CH;
constexpr int MAXS = (MAXC + SC - 1) / SC;
constexpr int CAP  = 6144;
constexpr int DYN_BYTES = CAP * 8 * 2 + 1024 * 8 + CAP * 4 * 2;  // 155648

__device__ float  g_proj[MAXN];
__device__ float  g_sorted[MAXN];
__device__ double g_xs[MAXN + 2];
__device__ int    g_lh_idx[MAXN];
__device__ double g_lh_val[MAXN];
__device__ int    g_lhn[MAXC];
__device__ int    g_uh_idx[MAXN];
__device__ double g_uh_val[MAXN];
__device__ int    g_uhn[MAXC];
__device__ int    g_slh_idx[MAXN];
__device__ double g_slh_val[MAXN];
__device__ int    g_slhn[MAXS];
__device__ int    g_suh_idx[MAXN];
__device__ double g_suh_val[MAXN];
__device__ int    g_suhn[MAXS];
__device__ int    g_Hidx[MAXN + 2];     // fallback scratch (lower)
__device__ double g_Hval[MAXN + 2];
__device__ int    g_Sidx[MAXN + 2];     // fallback scratch (upper)
__device__ double g_Sval[MAXN + 2];
__device__ unsigned char g_cub_tmp[1 << 24];

// ---------------- matvec: one warp per row, D=128 ----------------
__global__ void k_matvec(const float* __restrict__ X, const float* __restrict__ PV,
                         const int* __restrict__ IDX, int N) {
    __shared__ __align__(16) float sp[128];
    int pidx = IDX[0];
    if (threadIdx.x < 128) sp[threadIdx.x] = PV[pidx * 128 + threadIdx.x];
    __syncthreads();
    int g    = blockIdx.x * blockDim.x + threadIdx.x;
    int row  = g >> 5;
    int lane = g & 31;
    if (row >= N) return;
    const float4* xr = reinterpret_cast<const float4*>(X) + (size_t)row * 32;
    float4 a = xr[lane];
    float4 b = reinterpret_cast<const float4*>(sp)[lane];
    float s = a.x * b.x + a.y * b.y + a.z * b.z + a.w * b.w;
#pragma unroll
    for (int o = 16; o; o >>= 1) s += __shfl_xor_sync(0xffffffffu, s, o);
    if (lane == 0) g_proj[row] = s;
}

__global__ void k_convert(int N) {
    int i = blockIdx.x * blockDim.x + threadIdx.x;
    if (i < N) g_xs[i + 1] = (double)g_sorted[i];
    if (i == 0) g_xs[0] = 0.0;
}

// In-place strict monotone-chain over pre-staged candidates (processing order).
// Pop inequality is the exact reference one (equality pops collinear points).
// Works for the upper hull when candidates are in decreasing-index order.
// In-place safe: stack write position m <= read position r always.
__device__ __forceinline__ int merge_inplace(int* idx, double* val, int n) {
    int m = 0, ai = 0, bi = 0; double av = 0.0, bv = 0.0;
    for (int r = 0; r < n; r++) {
        int ci = idx[r]; double cv = val[r];
        while (m >= 2) {
            if ((cv - bv) * (double)(bi - ai) < (bv - av) * (double)(ci - bi)) break;
            m--; bi = ai; bv = av;
            if (m >= 2) { ai = idx[m - 2]; av = val[m - 2]; }
        }
        idx[m] = ci; val[m] = cv;
        ai = bi; av = bv; bi = ci; bv = cv; m++;
    }
    return m;
}

// Per-chunk strict hulls, all in shared memory.
__global__ void k_chunk_hulls(int N) {
    __shared__ int    sliL[CH]; __shared__ double slvL[CH];
    __shared__ int    sliU[CH]; __shared__ double slvU[CH];
    __shared__ int smL, smU;
    int c = blockIdx.x, tid = threadIdx.x;
    int s = c * CH + 1;
    int e = min((c + 1) * CH, N);
    int n = e - s + 1;
    for (int k = tid; k < n; k += blockDim.x) {
        double v = g_xs[s + k];
        sliL[k] = s + k;       slvL[k] = v;
        sliU[n - 1 - k] = s + k; slvU[n - 1 - k] = v;   // descending order
    }
    __syncthreads();
    if (tid == 0)  smL = merge_inplace(sliL, slvL, n);
    if (tid == 64) smU = merge_inplace(sliU, slvU, n);
    __syncthreads();
    int base = c * CH;
    for (int k = tid; k < smL; k += blockDim.x) { g_lh_idx[base + k] = sliL[k]; g_lh_val[base + k] = slvL[k]; }
    for (int k = tid; k < smU; k += blockDim.x) { g_uh_idx[base + k] = sliU[k]; g_uh_val[base + k] = slvU[k]; }
    if (tid == 0)  g_lhn[c] = smL;
    if (tid == 64) g_uhn[c] = smU;
}

// Superchunk hulls: merge SC chunk hulls (done once).
__global__ void k_super_hulls(int N, int nchunk) {
    __shared__ int    sIdx0[SCAP]; __shared__ double sVal0[SCAP];
    __shared__ int    sIdx1[SCAP]; __shared__ double sVal1[SCAP];
    __shared__ int offL[SC + 1], offU[SC + 1];
    __shared__ int totL, totU, mL, mU;
    __shared__ int* pIL; __shared__ double* pVL; __shared__ int* pIU; __shared__ double* pVU;
    int sblk = blockIdx.x, tid = threadIdx.x;
    int c0 = sblk * SC;
    int c1 = min(c0 + SC, nchunk);
    int nc = c1 - c0;
    int gbase = c0 * CH;
    if (tid == 0) {
        int o = 0;
        for (int c = c0; c < c1; c++) { offL[c - c0] = o; o += g_lhn[c]; }
        totL = o;
        pIL = (o <= SCAP) ? sIdx0 : (g_slh_idx + gbase);
        pVL = (o <= SCAP) ? sVal0 : (g_slh_val + gbase);
    }
    if (tid == 32) {
        int o = 0;
        for (int c = c1 - 1; c >= c0; c--) { offU[c1 - 1 - c] = o; o += g_uhn[c]; }
        totU = o;
        pIU = (o <= SCAP) ? sIdx1 : (g_suh_idx + gbase);
        pVU = (o <= SCAP) ? sVal1 : (g_suh_val + gbase);
    }
    __syncthreads();
    for (int j = 0; j < nc; j++) {
        int c = c0 + j;
        int srcb = c * CH, len = g_lhn[c], dst = offL[j];
        for (int k = tid; k < len; k += blockDim.x) { pIL[dst + k] = g_lh_idx[srcb + k]; pVL[dst + k] = g_lh_val[srcb + k]; }
        int cu = c1 - 1 - j;
        int srcbu = cu * CH, lenu = g_uhn[cu], dstu = offU[j];
        for (int k = tid; k < lenu; k += blockDim.x) { pIU[dstu + k] = g_uh_idx[srcbu + k]; pVU[dstu + k] = g_uh_val[srcbu + k]; }
    }
    __syncthreads();
    if (tid == 0)  mL = merge_inplace(pIL, pVL, totL);
    if (tid == 32) mU = merge_inplace(pIU, pVU, totU);
    __syncthreads();
    for (int k = tid; k < mL; k += blockDim.x) { g_slh_idx[gbase + k] = pIL[k]; g_slh_val[gbase + k] = pVL[k]; }
    for (int k = tid; k < mU; k += blockDim.x) { g_suh_idx[gbase + k] = pIU[k]; g_suh_val[gbase + k] = pVU[k]; }
    if (tid == 0)  g_slhn[sblk] = mL;
    if (tid == 32) g_suhn[sblk] = mU;
}

__device__ __forceinline__ double block_max(double v, double* red, int tid) {
    red[tid] = v;
    __syncthreads();
    for (int s = 512; s > 0; s >>= 1) {
        if (tid < s) { double o = red[tid + s]; if (o > red[tid]) red[tid] = o; }
        __syncthreads();
    }
    double r = red[0];
    __syncthreads();
    return r;
}

__global__ void __launch_bounds__(1024, 1) k_dip(int N, int nchunk, int nsuper, float* out) {
    extern __shared__ unsigned char dyn[];
    double* dValL = (double*)dyn;                 // CAP
    double* dValU = dValL + CAP;                  // CAP
    double* red   = dValU + CAP;                  // 1024
    int*    dIdxL = (int*)(red + 1024);           // CAP
    int*    dIdxU = dIdxL + CAP;                  // CAP

    __shared__ int s_low, s_high, s_done;
    __shared__ double s_dip;
    __shared__ int nsL, nsU, totL, totU, s_mL, s_mU, s_lg, s_ll, s_ig, s_ih;
    __shared__ int4 srcL[40], srcU[40];
    __shared__ int* pIL; __shared__ double* pVL; __shared__ int* pIU; __shared__ double* pVU;

    int tid = threadIdx.x;
    if (tid == 0) { s_low = 1; s_high = N; s_dip = 1.0; s_done = 0; }
    __syncthreads();
    if (N < 4 || g_xs[1] == g_xs[N]) {
        if (tid == 0) out[0] = (float)(1.0 / (2.0 * (double)(N > 0 ? N : 1)));
        return;
    }

    for (int iter = 0; iter < 64; iter++) {
        int low = s_low, high = s_high;

        // -------- source lists --------
        if (tid == 0) {
            int hc = (high - 1) / CH;
            int sc = hc / SC;
            int ns = 0, o = 0;
            for (int s = 0; s < sc; s++)         { int l = g_slhn[s]; srcL[ns] = make_int4(1, s * SC * CH, l, o); ns++; o += l; }
            for (int c = sc * SC; c < hc; c++)   { int l = g_lhn[c];  srcL[ns] = make_int4(0, c * CH, l, o); ns++; o += l; }
            int rb = hc * CH + 1, rl = high - hc * CH;
            srcL[ns] = make_int4(2, rb, rl, o); ns++; o += rl;
            nsL = ns; totL = o;
            pIL = (o <= CAP) ? dIdxL : g_Hidx;
            pVL = (o <= CAP) ? dValL : g_Hval;
        }
        if (tid == 32) {
            int lc = (low - 1) / CH;
            int scU = (lc + SC) / SC;                        // ceil((lc+1)/SC)
            int ns = 0, o = 0;
            for (int s = nsuper - 1; s >= scU; s--) { int l = g_suhn[s]; srcU[ns] = make_int4(4, s * SC * CH, l, o); ns++; o += l; }
            int ctop = min(scU * SC, nchunk) - 1;
            for (int c = ctop; c >= lc + 1; c--)    { int l = g_uhn[c];  srcU[ns] = make_int4(3, c * CH, l, o); ns++; o += l; }
            int rb = min((lc + 1) * CH, N), rl = rb - low + 1;
            srcU[ns] = make_int4(5, rb, rl, o); ns++; o += rl;
            nsU = ns; totU = o;
            pIU = (o <= CAP) ? dIdxU : g_Sidx;
            pVU = (o <= CAP) ? dValU : g_Sval;
        }
        __syncthreads();

        // -------- stage candidates (all threads) --------
        {
            int* IL = pIL; double* VL = pVL;
            for (int j = 0; j < nsL; j++) {
                int4 sd = srcL[j];
                if (sd.x == 2)       for (int k = tid; k < sd.z; k += 1024) { IL[sd.w + k] = sd.y + k;           VL[sd.w + k] = g_xs[sd.y + k]; }
                else if (sd.x == 0)  for (int k = tid; k < sd.z; k += 1024) { IL[sd.w + k] = g_lh_idx[sd.y + k]; VL[sd.w + k] = g_lh_val[sd.y + k]; }
                else                 for (int k = tid; k < sd.z; k += 1024) { IL[sd.w + k] = g_slh_idx[sd.y + k]; VL[sd.w + k] = g_slh_val[sd.y + k]; }
            }
            int* IU = pIU; double* VU = pVU;
            for (int j = 0; j < nsU; j++) {
                int4 sd = srcU[j];
                if (sd.x == 5)       for (int k = tid; k < sd.z; k += 1024) { IU[sd.w + k] = sd.y - k;           VU[sd.w + k] = g_xs[sd.y - k]; }
                else if (sd.x == 3)  for (int k = tid; k < sd.z; k += 1024) { IU[sd.w + k] = g_uh_idx[sd.y + k]; VU[sd.w + k] = g_uh_val[sd.y + k]; }
                else                 for (int k = tid; k < sd.z; k += 1024) { IU[sd.w + k] = g_suh_idx[sd.y + k]; VU[sd.w + k] = g_suh_val[sd.y + k]; }
            }
        }
        __syncthreads();

        // -------- merges + chain truncation --------
        if (tid == 0) {
            int m = merge_inplace(pIL, pVL, totL);
            int lo2 = 0, hi2 = m - 1;
            while (lo2 < hi2) { int mid = (lo2 + hi2 + 1) >> 1; if (pIL[mid] <= low) lo2 = mid; else hi2 = mid - 1; }
            s_mL = m; s_lg = m - lo2;
        }
        if (tid == 32) {
            int m = merge_inplace(pIU, pVU, totU);
            int lo2 = 0, hi2 = m - 1;
            while (lo2 < hi2) { int mid = (lo2 + hi2 + 1) >> 1; if (pIU[mid] >= high) lo2 = mid; else hi2 = mid - 1; }
            s_mU = m; s_ll = m - lo2;
        }
        __syncthreads();

        int mL = s_mL, mU = s_mU, lg = s_lg, ll = s_ll;
        // chain mapping: gcm[i] = pIL[mL - i] (i=1..lg), lcm[i] = pIU[mU - i] (i=1..ll)

        // -------- d-walk (verbatim reference port) --------
        if (tid == 0) {
            int ig = lg, ih = ll, ix = lg - 1, iv = 2;
            double d = 0.0;
            if (!(lg == 2 && ll == 2)) {
                long long guard = 4LL * N + 16;
                while (guard-- > 0) {
                    int gcmix = pIL[mL - ix], lcmiv = pIU[mU - iv];
                    if (gcmix > lcmiv) {
                        int gcmi1 = pIL[mL - ix - 1];
                        double xg = pVL[mL - ix], xg1 = pVL[mL - ix - 1], xl = pVU[mU - iv];
                        double t = (double)(lcmiv - gcmi1 + 1) - (xl - xg1) * (double)(gcmix - gcmi1) / (xg - xg1);
                        iv++;
                        if (t >= d) { d = t; ig = ix + 1; ih = iv - 1; }
                    } else {
                        int lcmiv1 = pIU[mU - iv + 1];
                        double xg = pVL[mL - ix], xl = pVU[mU - iv], xl1 = pVU[mU - iv + 1];
                        double t = (xg - xl1) * (double)(lcmiv - lcmiv1) / (xl - xl1) - (double)(gcmix - lcmiv1 - 1);
                        ix--;
                        if (t > d) { d = t; ig = ix + 1; ih = iv; }
                    }
                    if (ix < 1) ix = 1;
                    if (iv > ll) iv = ll;
                    if (pIL[mL - ix] == pIU[mU - iv]) break;
                }
            } else d = 1.0;
            s_ig = ig; s_ih = ih;
            if (d < s_dip) s_done = 1;
        }
        __syncthreads();
        if (s_done) break;

        // -------- fused parallel segment scans --------
        int ig = s_ig, ih = s_ih;
        double lmax = -1e308, umax = -1e308;

        if (lg > ig) {   // segments t: jb=pIL[base+t], je=pIL[base+t+1]; covers [gcm[lg], gcm[ig]]
            int base = mL - lg;
            int nseg = lg - ig;
            int A = pIL[base], B = pIL[base + nseg];
            int total = B - A + 1;
            int per = (total + 1023) / 1024;
            int lo = A + tid * per;
            int hi = min(lo + per - 1, B);
            if (lo <= hi) {
                int lo2 = 0, hi2 = nseg - 1;
                while (lo2 < hi2) { int mid = (lo2 + hi2 + 1) >> 1; if (pIL[base + mid] <= lo) lo2 = mid; else hi2 = mid - 1; }
                int t = lo2;
                int jb = pIL[base + t], je = pIL[base + t + 1];
                double xjb = pVL[base + t], xje = pVL[base + t + 1];
                bool valid = (je - jb > 1) && (xje != xjb);
                double C = valid ? (double)(je - jb) / (xje - xjb) : 0.0;
                for (int i = lo; i <= hi; i++) {
                    while (i > je && t < nseg - 1) {
                        t++; jb = je; xjb = xje;
                        je = pIL[base + t + 1]; xje = pVL[base + t + 1];
                        valid = (je - jb > 1) && (xje != xjb);
                        C = valid ? (double)(je - jb) / (xje - xjb) : 0.0;
                    }
                    if (valid) {
                        double tt = (double)(i - jb + 1) - (g_xs[i] - xjb) * C;
                        if (tt > lmax) lmax = tt;
                    }
                }
            }
        }
        if (ll > ih) {   // segments t: jb=pIU[baseU-t], je=pIU[baseU-t-1]; covers [lcm[ih], lcm[ll]]
            int baseU = mU - ih;
            int nseg = ll - ih;
            int A = pIU[baseU], B = pIU[baseU - nseg];
            int total = B - A + 1;
            int per = (total + 1023) / 1024;
            int lo = A + tid * per;
            int hi = min(lo + per - 1, B);
            if (lo <= hi) {
                int lo2 = 0, hi2 = nseg - 1;
                while (lo2 < hi2) { int mid = (lo2 + hi2 + 1) >> 1; if (pIU[baseU - mid] <= lo) lo2 = mid; else hi2 = mid - 1; }
                int t = lo2;
                int jb = pIU[baseU - t], je = pIU[baseU - t - 1];
                double xjb = pVU[baseU - t], xje = pVU[baseU - t - 1];
                bool valid = (je - jb > 1) && (xje != xjb);
                double C = valid ? (double)(je - jb) / (xje - xjb) : 0.0;
                for (int i = lo; i <= hi; i++) {
                    while (i > je && t < nseg - 1) {
                        t++; jb = je; xjb = xje;
                        je = pIU[baseU - t - 1]; xje = pVU[baseU - t - 1];
                        valid = (je - jb > 1) && (xje != xjb);
                        C = valid ? (double)(je - jb) / (xje - xjb) : 0.0;
                    }
                    if (valid) {
                        double tt = (g_xs[i] - xjb) * C - (double)(i - jb - 1);
                        if (tt > umax) umax = tt;
                    }
                }
            }
        }

        double rl = block_max(lmax, red, tid);
        double ru = block_max(umax, red, tid);

        if (tid == 0) {
            double dl = (lg > ig) ? ((rl > 1.0) ? rl : 1.0) : 0.0;
            double du = (ll > ih) ? ((ru > 1.0) ? ru : 1.0) : 0.0;
            double dn = (du > dl) ? du : dl;
            if (s_dip < dn) s_dip = dn;
            int nl = pIL[mL - s_ig], nh = pIU[mU - s_ih];
            if ((s_low == nl && s_high == nh) || nl >= nh) s_done = 1;
            else { s_low = nl; s_high = nh; }
        }
        __syncthreads();
        if (s_done) break;
    }
    __syncthreads();
    if (tid == 0) out[0] = (float)(s_dip / (2.0 * (double)N));
}

// ---------------------------------------------------------------------------
extern "C" void kernel_launch(void* const* d_in, const int* in_sizes, int n_in,
                              void* d_out, int out_size) {
    const float* X   = (const float*)d_in[0];
    const float* PV  = (const float*)d_in[1];
    const int*   IDX = (const int*)d_in[2];

    const int D = 128;
    int N = in_sizes[0] / D;
    if (N <= 0 || N > MAXN) return;

    float* proj = nullptr;
    float* sorted = nullptr;
    void*  tmp = nullptr;
    cudaGetSymbolAddress((void**)&proj, g_proj);
    cudaGetSymbolAddress((void**)&sorted, g_sorted);
    cudaGetSymbolAddress(&tmp, g_cub_tmp);

    static bool attr_done = false;
    if (!attr_done) {
        cudaFuncSetAttribute(k_dip, cudaFuncAttributeMaxDynamicSharedMemorySize, DYN_BYTES);
        attr_done = true;
    }

    k_matvec<<<(N * 32 + 255) / 256, 256>>>(X, PV, IDX, N);

    size_t tb = 0;
    cub::DeviceRadixSort::SortKeys(nullptr, tb, proj, sorted, N);
    if (tb > sizeof(g_cub_tmp)) return;
    cub::DeviceRadixSort::SortKeys(tmp, tb, proj, sorted, N);

    k_convert<<<(N + 255) / 256, 256>>>(N);

    int nchunk = (N + CH - 1) / CH;
    int nsuper = (nchunk + SC - 1) / SC;
    k_chunk_hulls<<<nchunk, 128>>>(N);
    k_super_hulls<<<nsuper, 256>>>(N, nchunk);

    k_dip<<<1, 1024, DYN_BYTES>>>(N, nchunk, nsuper, (float*)d_out);
}

// round 6
// speedup vs baseline: 1.7560x; 1.7560x over previous
#include <cuda_runtime.h>
#include <cuda_bf16.h>
#include <cub/cub.cuh>

#define CH 256
#define SC 16
#define HC 8
constexpr int MAXN = 1 << 18;
constexpr int MAXC = MAXN / CH;          // 1024
constexpr int MAXS = MAXC / SC;          // 64
constexpr int MAXH = MAXS / HC;          // 8
constexpr int CAP  = 5120;
constexpr int DIP_DYN = CAP * 32 + 4096;         // vals(8)*2 + f32(4)*2 + idx(4)*2 per side pair + red
constexpr int LVL_DYN_MAX = 3072 * 32;

__device__ float  g_proj[MAXN];
__device__ float  g_sorted[MAXN];
// level 0 (chunk) hulls
__device__ int    g_lh_idx[MAXN];  __device__ double g_lh_val[MAXN];  __device__ int g_lhn[MAXC];
__device__ int    g_uh_idx[MAXN];  __device__ double g_uh_val[MAXN];  __device__ int g_uhn[MAXC];
// level 1 (super = 16 chunks)
__device__ int    g_slh_idx[MAXN]; __device__ double g_slh_val[MAXN]; __device__ int g_slhn[MAXS];
__device__ int    g_suh_idx[MAXN]; __device__ double g_suh_val[MAXN]; __device__ int g_suhn[MAXS];
// level 2 (hyper = 8 supers)
__device__ int    g_hlh_idx[MAXN]; __device__ double g_hlh_val[MAXN]; __device__ int g_hlhn[MAXH];
__device__ int    g_huh_idx[MAXN]; __device__ double g_huh_val[MAXN]; __device__ int g_huhn[MAXH];
// k_dip overflow fallback
__device__ int    g_Hidx[MAXN + 2]; __device__ double g_Hval[MAXN + 2]; __device__ float g_Hv32[MAXN + 2];
__device__ int    g_Sidx[MAXN + 2]; __device__ double g_Sval[MAXN + 2]; __device__ float g_Sv32[MAXN + 2];
__device__ unsigned char g_cub_tmp[1 << 24];

// ---------------- matvec: one warp per row, D=128 ----------------
__global__ void k_matvec(const float* __restrict__ X, const float* __restrict__ PV,
                         const int* __restrict__ IDX, int N) {
    __shared__ __align__(16) float sp[128];
    int pidx = IDX[0];
    if (threadIdx.x < 128) sp[threadIdx.x] = PV[pidx * 128 + threadIdx.x];
    __syncthreads();
    int g    = blockIdx.x * blockDim.x + threadIdx.x;
    int row  = g >> 5;
    int lane = g & 31;
    if (row >= N) return;
    const float4* xr = reinterpret_cast<const float4*>(X) + (size_t)row * 32;
    float4 a = xr[lane];
    float4 b = reinterpret_cast<const float4*>(sp)[lane];
    float s = a.x * b.x + a.y * b.y + a.z * b.z + a.w * b.w;
#pragma unroll
    for (int o = 16; o; o >>= 1) s += __shfl_xor_sync(0xffffffffu, s, o);
    if (lane == 0) g_proj[row] = s;
}

// ---------------- strict monotone-chain merges ----------------
// Reference pop rule: break iff (cv-bv)*(bi-ai) < (bv-av)*(ci-bi)  [f64].
// f32-filtered variant: decide in f32 when outside a provably safe margin,
// fall back to the exact reference f64 comparison otherwise. All values are
// exact binary32, so |p_f32 - p_f64| <= ~2.4e-7*|p|; eps=4e-7 covers it.
__device__ __forceinline__ int merge_f32(int* idx, double* val, float* v32, int n) {
    int m = 0, ai = 0, bi = 0; double av = 0.0, bv = 0.0; float af = 0.f, bf = 0.f;
    for (int r = 0; r < n; r++) {
        int ci = idx[r]; double cv = val[r]; float cf = v32[r];
        while (m >= 2) {
            float p1 = (cf - bf) * (float)(bi - ai);
            float p2 = (bf - af) * (float)(ci - bi);
            float eps = 4e-7f * (fabsf(p1) + fabsf(p2)) + 1e-33f;
            bool brk;
            float diff = p1 - p2;
            if (diff < -eps) brk = true;
            else if (diff > eps) brk = false;
            else brk = ((cv - bv) * (double)(bi - ai)) < ((bv - av) * (double)(ci - bi));
            if (brk) break;
            m--; bi = ai; bv = av; bf = af;
            if (m >= 2) { ai = idx[m - 2]; av = val[m - 2]; af = v32[m - 2]; }
        }
        idx[m] = ci; val[m] = cv; v32[m] = cf;
        ai = bi; av = bv; af = bf; bi = ci; bv = cv; bf = cf; m++;
    }
    return m;
}
__device__ __forceinline__ int merge_f64(int* idx, double* val, int n) {
    int m = 0, ai = 0, bi = 0; double av = 0.0, bv = 0.0;
    for (int r = 0; r < n; r++) {
        int ci = idx[r]; double cv = val[r];
        while (m >= 2) {
            if ((cv - bv) * (double)(bi - ai) < (bv - av) * (double)(ci - bi)) break;
            m--; bi = ai; bv = av;
            if (m >= 2) { ai = idx[m - 2]; av = val[m - 2]; }
        }
        idx[m] = ci; val[m] = cv;
        ai = bi; av = bv; bi = ci; bv = cv; m++;
    }
    return m;
}

// ---------------- level 0: per-chunk strict hulls ----------------
__global__ void k_chunk_hulls(int N) {
    __shared__ int    iL[CH]; __shared__ double vL[CH]; __shared__ float fL[CH];
    __shared__ int    iU[CH]; __shared__ double vU[CH]; __shared__ float fU[CH];
    __shared__ int smL, smU;
    int c = blockIdx.x, tid = threadIdx.x;
    int s = c * CH + 1;
    int e = min((c + 1) * CH, N);
    int n = e - s + 1;
    for (int k = tid; k < n; k += blockDim.x) {
        float x = g_sorted[s + k - 1];
        iL[k] = s + k;            vL[k] = (double)x;            fL[k] = x;
        iU[n - 1 - k] = s + k;    vU[n - 1 - k] = (double)x;    fU[n - 1 - k] = x;
    }
    __syncthreads();
    if (tid == 0)  smL = merge_f32(iL, vL, fL, n);
    if (tid == 64) smU = merge_f32(iU, vU, fU, n);
    __syncthreads();
    int base = c * CH;
    for (int k = tid; k < smL; k += blockDim.x) { g_lh_idx[base + k] = iL[k]; g_lh_val[base + k] = vL[k]; }
    for (int k = tid; k < smU; k += blockDim.x) { g_uh_idx[base + k] = iU[k]; g_uh_val[base + k] = vU[k]; }
    if (tid == 0)  g_lhn[c] = smL;
    if (tid == 64) g_uhn[c] = smU;
}

// ---------------- generic level merge (chunks->supers, supers->hypers) ----------------
__global__ void k_level(const int* sLi, const double* sLv, const int* sLn,
                        int* dLi, double* dLv, int* dLn,
                        const int* sUi, const double* sUv, const int* sUn,
                        int* dUi, double* dUv, int* dUn,
                        int group, int srcStride, int dstStride, int nsrc, int cap) {
    extern __shared__ unsigned char sm[];
    double* vL = (double*)sm;
    double* vU = vL + cap;
    float*  fL = (float*)(vU + cap);
    float*  fU = fL + cap;
    int*    iL = (int*)(fU + cap);
    int*    iU = iL + cap;
    __shared__ int offL[24], offU[24];
    __shared__ int totL, totU, mL, mU, fbL, fbU;
    int b = blockIdx.x, tid = threadIdx.x;
    int j0 = b * group, j1 = min(j0 + group, nsrc), nj = j1 - j0;
    if (tid == 0) {
        int o = 0;
        for (int j = j0; j < j1; j++) { offL[j - j0] = o; o += sLn[j]; }
        totL = o; fbL = (o > cap);
    }
    if (tid == 32) {
        int o = 0;
        for (int j = j1 - 1; j >= j0; j--) { offU[j1 - 1 - j] = o; o += sUn[j]; }
        totU = o; fbU = (o > cap);
    }
    __syncthreads();
    size_t db = (size_t)b * dstStride;
    for (int j = 0; j < nj; j++) {
        int src = (j0 + j) * srcStride, len = sLn[j0 + j], dst = offL[j];
        if (!fbL) for (int k = tid; k < len; k += blockDim.x) { iL[dst + k] = sLi[src + k]; double v = sLv[src + k]; vL[dst + k] = v; fL[dst + k] = (float)v; }
        else      for (int k = tid; k < len; k += blockDim.x) { dLi[db + dst + k] = sLi[src + k]; dLv[db + dst + k] = sLv[src + k]; }
        int ju = j1 - 1 - j;
        int srcu = ju * srcStride, lenu = sUn[ju], dstu = offU[j];
        if (!fbU) for (int k = tid; k < lenu; k += blockDim.x) { iU[dstu + k] = sUi[srcu + k]; double v = sUv[srcu + k]; vU[dstu + k] = v; fU[dstu + k] = (float)v; }
        else      for (int k = tid; k < lenu; k += blockDim.x) { dUi[db + dstu + k] = sUi[srcu + k]; dUv[db + dstu + k] = sUv[srcu + k]; }
    }
    __syncthreads();
    if (tid == 0)  mL = fbL ? merge_f64(dLi + db, dLv + db, totL) : merge_f32(iL, vL, fL, totL);
    if (tid == 32) mU = fbU ? merge_f64(dUi + db, dUv + db, totU) : merge_f32(iU, vU, fU, totU);
    __syncthreads();
    if (!fbL) for (int k = tid; k < mL; k += blockDim.x) { dLi[db + k] = iL[k]; dLv[db + k] = vL[k]; }
    if (!fbU) for (int k = tid; k < mU; k += blockDim.x) { dUi[db + k] = iU[k]; dUv[db + k] = vU[k]; }
    if (tid == 0)  dLn[b] = mL;
    if (tid == 32) dUn[b] = mU;
}

__device__ __forceinline__ float block_maxf(float v, float* red, int tid) {
    red[tid] = v;
    __syncthreads();
    for (int s = 512; s > 0; s >>= 1) {
        if (tid < s) { float o = red[tid + s]; if (o > red[tid]) red[tid] = o; }
        __syncthreads();
    }
    float r = red[0];
    __syncthreads();
    return r;
}

__global__ void __launch_bounds__(1024, 1) k_dip(int N, int nchunk, int nsuper, int nhyper, float* out) {
    extern __shared__ unsigned char dyn[];
    double* dValL = (double*)dyn;                  // CAP
    double* dValU = dValL + CAP;                   // CAP
    float*  dF32L = (float*)(dValU + CAP);         // CAP
    float*  dF32U = dF32L + CAP;                   // CAP
    float*  red   = dF32U + CAP;                   // 1024
    int*    dIdxL = (int*)(red + 1024);            // CAP
    int*    dIdxU = dIdxL + CAP;                   // CAP

    __shared__ int s_low, s_high, s_done;
    __shared__ double s_dip;
    __shared__ int nsL, nsU, totL, totU, s_mL, s_mU, s_lg, s_ll, s_ig, s_ih;
    __shared__ int4 srcL[40], srcU[40];
    __shared__ int* pIL; __shared__ double* pVL; __shared__ float* pFL;
    __shared__ int* pIU; __shared__ double* pVU; __shared__ float* pFU;

    int tid = threadIdx.x;
    if (tid == 0) { s_low = 1; s_high = N; s_dip = 1.0; s_done = 0; }
    __syncthreads();
    if (N < 4 || g_sorted[0] == g_sorted[N - 1]) {
        if (tid == 0) out[0] = (float)(1.0 / (2.0 * (double)(N > 0 ? N : 1)));
        return;
    }

    for (int iter = 0; iter < 64; iter++) {
        int low = s_low, high = s_high;

        // -------- source lists --------
        if (tid == 0) {
            int hc = (high - 1) / CH;          // full chunks [0, hc); partial chunk hc
            int nH = hc / (HC * SC);           // full hypers [0, nH)
            int nS = hc / SC;                  // full supers [nH*HC, nS)
            int ns = 0, o = 0;
            for (int h = 0; h < nH; h++)        { int l = g_hlhn[h]; srcL[ns] = make_int4(6, h * HC * SC * CH, l, o); ns++; o += l; }
            for (int s = nH * HC; s < nS; s++)  { int l = g_slhn[s]; srcL[ns] = make_int4(1, s * SC * CH, l, o); ns++; o += l; }
            for (int c = nS * SC; c < hc; c++)  { int l = g_lhn[c];  srcL[ns] = make_int4(0, c * CH, l, o); ns++; o += l; }
            int rb = hc * CH + 1, rl = high - hc * CH;
            srcL[ns] = make_int4(2, rb, rl, o); ns++; o += rl;
            nsL = ns; totL = o;
            bool fb = (o > CAP);
            pIL = fb ? g_Hidx : dIdxL; pVL = fb ? g_Hval : dValL; pFL = fb ? g_Hv32 : dF32L;
        }
        if (tid == 32) {
            int lc = (low - 1) / CH;           // partial chunk containing low
            int cfirst = lc + 1;
            int sS = (cfirst + SC - 1) / SC;
            int hH = (cfirst + HC * SC - 1) / (HC * SC);
            int send = min(hH * HC, nsuper);
            int cend = min(sS * SC, nchunk);
            int ns = 0, o = 0;
            for (int h = nhyper - 1; h >= hH; h--)   { int l = g_huhn[h]; srcU[ns] = make_int4(7, h * HC * SC * CH, l, o); ns++; o += l; }
            for (int s = send - 1; s >= sS; s--)     { int l = g_suhn[s]; srcU[ns] = make_int4(4, s * SC * CH, l, o); ns++; o += l; }
            for (int c = cend - 1; c >= cfirst; c--) { int l = g_uhn[c];  srcU[ns] = make_int4(3, c * CH, l, o); ns++; o += l; }
            int rb = min(cfirst * CH, N), rl = rb - low + 1;
            srcU[ns] = make_int4(5, rb, rl, o); ns++; o += rl;
            nsU = ns; totU = o;
            bool fb = (o > CAP);
            pIU = fb ? g_Sidx : dIdxU; pVU = fb ? g_Sval : dValU; pFU = fb ? g_Sv32 : dF32U;
        }
        __syncthreads();

        // -------- stage candidates (all 1024 threads) --------
        {
            int* IL = pIL; double* VL = pVL; float* FL = pFL;
            for (int j = 0; j < nsL; j++) {
                int4 sd = srcL[j];
                if (sd.x == 2) {
                    for (int k = tid; k < sd.z; k += 1024) {
                        float x = g_sorted[sd.y + k - 1];
                        IL[sd.w + k] = sd.y + k; VL[sd.w + k] = (double)x; FL[sd.w + k] = x;
                    }
                } else {
                    const int* si; const double* sv;
                    if (sd.x == 0)      { si = g_lh_idx;  sv = g_lh_val; }
                    else if (sd.x == 1) { si = g_slh_idx; sv = g_slh_val; }
                    else                { si = g_hlh_idx; sv = g_hlh_val; }
                    for (int k = tid; k < sd.z; k += 1024) {
                        double v = sv[sd.y + k];
                        IL[sd.w + k] = si[sd.y + k]; VL[sd.w + k] = v; FL[sd.w + k] = (float)v;
                    }
                }
            }
            int* IU = pIU; double* VU = pVU; float* FU = pFU;
            for (int j = 0; j < nsU; j++) {
                int4 sd = srcU[j];
                if (sd.x == 5) {
                    for (int k = tid; k < sd.z; k += 1024) {
                        float x = g_sorted[sd.y - k - 1];
                        IU[sd.w + k] = sd.y - k; VU[sd.w + k] = (double)x; FU[sd.w + k] = x;
                    }
                } else {
                    const int* si; const double* sv;
                    if (sd.x == 3)      { si = g_uh_idx;  sv = g_uh_val; }
                    else if (sd.x == 4) { si = g_suh_idx; sv = g_suh_val; }
                    else                { si = g_huh_idx; sv = g_huh_val; }
                    for (int k = tid; k < sd.z; k += 1024) {
                        double v = sv[sd.y + k];
                        IU[sd.w + k] = si[sd.y + k]; VU[sd.w + k] = v; FU[sd.w + k] = (float)v;
                    }
                }
            }
        }
        __syncthreads();

        // -------- merges + chain truncation (two warps in parallel) --------
        if (tid == 0) {
            int m = merge_f32(pIL, pVL, pFL, totL);
            int lo2 = 0, hi2 = m - 1;
            while (lo2 < hi2) { int mid = (lo2 + hi2 + 1) >> 1; if (pIL[mid] <= low) lo2 = mid; else hi2 = mid - 1; }
            s_mL = m; s_lg = m - lo2;
        }
        if (tid == 32) {
            int m = merge_f32(pIU, pVU, pFU, totU);
            int lo2 = 0, hi2 = m - 1;
            while (lo2 < hi2) { int mid = (lo2 + hi2 + 1) >> 1; if (pIU[mid] >= high) lo2 = mid; else hi2 = mid - 1; }
            s_mU = m; s_ll = m - lo2;
        }
        __syncthreads();

        int mL = s_mL, mU = s_mU, lg = s_lg, ll = s_ll;
        // mapping: gcm[i] = pIL[mL - i] (i=1..lg), lcm[i] = pIU[mU - i] (i=1..ll)

        // -------- d-walk (verbatim reference port, f64) --------
        if (tid == 0) {
            int ig = lg, ih = ll, ix = lg - 1, iv = 2;
            double d = 0.0;
            if (!(lg == 2 && ll == 2)) {
                long long guard = 4LL * N + 16;
                while (guard-- > 0) {
                    int gcmix = pIL[mL - ix], lcmiv = pIU[mU - iv];
                    if (gcmix > lcmiv) {
                        int gcmi1 = pIL[mL - ix - 1];
                        double xg = pVL[mL - ix], xg1 = pVL[mL - ix - 1], xl = pVU[mU - iv];
                        double t = (double)(lcmiv - gcmi1 + 1) - (xl - xg1) * (double)(gcmix - gcmi1) / (xg - xg1);
                        iv++;
                        if (t >= d) { d = t; ig = ix + 1; ih = iv - 1; }
                    } else {
                        int lcmiv1 = pIU[mU - iv + 1];
                        double xg = pVL[mL - ix], xl = pVU[mU - iv], xl1 = pVU[mU - iv + 1];
                        double t = (xg - xl1) * (double)(lcmiv - lcmiv1) / (xl - xl1) - (double)(gcmix - lcmiv1 - 1);
                        ix--;
                        if (t > d) { d = t; ig = ix + 1; ih = iv; }
                    }
                    if (ix < 1) ix = 1;
                    if (iv > ll) iv = ll;
                    if (pIL[mL - ix] == pIU[mU - iv]) break;
                }
            } else d = 1.0;
            s_ig = ig; s_ih = ih;
            if (d < s_dip) s_done = 1;
        }
        __syncthreads();
        if (s_done) break;

        // -------- fused parallel segment scans, f32 --------
        int ig = s_ig, ih = s_ih;
        float lmax = -1e30f, umax = -1e30f;

        if (lg > ig) {   // segments t: jb=pIL[base+t], je=pIL[base+t+1]; covers [gcm[lg], gcm[ig]]
            int base = mL - lg;
            int nseg = lg - ig;
            int A = pIL[base], B = pIL[base + nseg];
            int total = B - A + 1;
            int per = (total + 1023) / 1024;
            int lo = A + tid * per;
            int hi = min(lo + per - 1, B);
            if (lo <= hi) {
                int lo2 = 0, hi2 = nseg - 1;
                while (lo2 < hi2) { int mid = (lo2 + hi2 + 1) >> 1; if (pIL[base + mid] <= lo) lo2 = mid; else hi2 = mid - 1; }
                int t = lo2;
                int jb = pIL[base + t], je = pIL[base + t + 1];
                float xjb = pFL[base + t], xje = pFL[base + t + 1];
                bool valid = (je - jb > 1) && (xje != xjb);
                float C = valid ? (float)(je - jb) / (xje - xjb) : 0.0f;
                for (int i = lo; i <= hi; i++) {
                    while (i > je && t < nseg - 1) {
                        t++; jb = je; xjb = xje;
                        je = pIL[base + t + 1]; xje = pFL[base + t + 1];
                        valid = (je - jb > 1) && (xje != xjb);
                        C = valid ? (float)(je - jb) / (xje - xjb) : 0.0f;
                    }
                    if (valid) {
                        float tt = (float)(i - jb + 1) - (g_sorted[i - 1] - xjb) * C;
                        if (tt > lmax) lmax = tt;
                    }
                }
            }
        }
        if (ll > ih) {   // segments t: jb=pIU[baseU-t], je=pIU[baseU-t-1]; covers [lcm[ih], lcm[ll]]
            int baseU = mU - ih;
            int nseg = ll - ih;
            int A = pIU[baseU], B = pIU[baseU - nseg];
            int total = B - A + 1;
            int per = (total + 1023) / 1024;
            int lo = A + tid * per;
            int hi = min(lo + per - 1, B);
            if (lo <= hi) {
                int lo2 = 0, hi2 = nseg - 1;
                while (lo2 < hi2) { int mid = (lo2 + hi2 + 1) >> 1; if (pIU[baseU - mid] <= lo) lo2 = mid; else hi2 = mid - 1; }
                int t = lo2;
                int jb = pIU[baseU - t], je = pIU[baseU - t - 1];
                float xjb = pFU[baseU - t], xje = pFU[baseU - t - 1];
                bool valid = (je - jb > 1) && (xje != xjb);
                float C = valid ? (float)(je - jb) / (xje - xjb) : 0.0f;
                for (int i = lo; i <= hi; i++) {
                    while (i > je && t < nseg - 1) {
                        t++; jb = je; xjb = xje;
                        je = pIU[baseU - t - 1]; xje = pFU[baseU - t - 1];
                        valid = (je - jb > 1) && (xje != xjb);
                        C = valid ? (float)(je - jb) / (xje - xjb) : 0.0f;
                    }
                    if (valid) {
                        float tt = (g_sorted[i - 1] - xjb) * C - (float)(i - jb - 1);
                        if (tt > umax) umax = tt;
                    }
                }
            }
        }

        float rl = block_maxf(lmax, red, tid);
        float ru = block_maxf(umax, red, tid);

        if (tid == 0) {
            double dl = (lg > ig) ? (((double)rl > 1.0) ? (double)rl : 1.0) : 0.0;
            double du = (ll > ih) ? (((double)ru > 1.0) ? (double)ru : 1.0) : 0.0;
            double dn = (du > dl) ? du : dl;
            if (s_dip < dn) s_dip = dn;
            int nl = pIL[mL - s_ig], nh = pIU[mU - s_ih];
            if ((s_low == nl && s_high == nh) || nl >= nh) s_done = 1;
            else { s_low = nl; s_high = nh; }
        }
        __syncthreads();
        if (s_done) break;
    }
    __syncthreads();
    if (tid == 0) out[0] = (float)(s_dip / (2.0 * (double)N));
}

// ---------------------------------------------------------------------------
extern "C" void kernel_launch(void* const* d_in, const int* in_sizes, int n_in,
                              void* d_out, int out_size) {
    const float* X   = (const float*)d_in[0];
    const float* PV  = (const float*)d_in[1];
    const int*   IDX = (const int*)d_in[2];

    const int D = 128;
    int N = in_sizes[0] / D;
    if (N <= 0 || N > MAXN) return;

    float* proj = nullptr;
    float* sorted = nullptr;
    void*  tmp = nullptr;
    cudaGetSymbolAddress((void**)&proj, g_proj);
    cudaGetSymbolAddress((void**)&sorted, g_sorted);
    cudaGetSymbolAddress(&tmp, g_cub_tmp);

    cudaFuncSetAttribute(k_dip,   cudaFuncAttributeMaxDynamicSharedMemorySize, DIP_DYN);
    cudaFuncSetAttribute(k_level, cudaFuncAttributeMaxDynamicSharedMemorySize, LVL_DYN_MAX);

    k_matvec<<<(N * 32 + 255) / 256, 256>>>(X, PV, IDX, N);

    size_t tb = 0;
    cub::DeviceRadixSort::SortKeys(nullptr, tb, proj, sorted, N);
    if (tb > sizeof(g_cub_tmp)) return;
    cub::DeviceRadixSort::SortKeys(tmp, tb, proj, sorted, N);

    int nchunk = (N + CH - 1) / CH;
    int nsuper = (nchunk + SC - 1) / SC;
    int nhyper = (nsuper + HC - 1) / HC;

    int *lh_i, *uh_i, *sl_i, *su_i, *hl_i, *hu_i;
    double *lh_v, *uh_v, *sl_v, *su_v, *hl_v, *hu_v;
    int *lhn, *uhn, *sln, *sun, *hln, *hun;
    cudaGetSymbolAddress((void**)&lh_i, g_lh_idx);  cudaGetSymbolAddress((void**)&lh_v, g_lh_val);  cudaGetSymbolAddress((void**)&lhn, g_lhn);
    cudaGetSymbolAddress((void**)&uh_i, g_uh_idx);  cudaGetSymbolAddress((void**)&uh_v, g_uh_val);  cudaGetSymbolAddress((void**)&uhn, g_uhn);
    cudaGetSymbolAddress((void**)&sl_i, g_slh_idx); cudaGetSymbolAddress((void**)&sl_v, g_slh_val); cudaGetSymbolAddress((void**)&sln, g_slhn);
    cudaGetSymbolAddress((void**)&su_i, g_suh_idx); cudaGetSymbolAddress((void**)&su_v, g_suh_val); cudaGetSymbolAddress((void**)&sun, g_suhn);
    cudaGetSymbolAddress((void**)&hl_i, g_hlh_idx); cudaGetSymbolAddress((void**)&hl_v, g_hlh_val); cudaGetSymbolAddress((void**)&hln, g_hlhn);
    cudaGetSymbolAddress((void**)&hu_i, g_huh_idx); cudaGetSymbolAddress((void**)&hu_v, g_huh_val); cudaGetSymbolAddress((void**)&hun, g_huhn);

    k_chunk_hulls<<<nchunk, 128>>>(N);
    k_level<<<nsuper, 256, 2048 * 32>>>(lh_i, lh_v, lhn, sl_i, sl_v, sln,
                                        uh_i, uh_v, uhn, su_i, su_v, sun,
                                        SC, CH, SC * CH, nchunk, 2048);
    k_level<<<nhyper, 256, 3072 * 32>>>(sl_i, sl_v, sln, hl_i, hl_v, hln,
                                        su_i, su_v, sun, hu_i, hu_v, hun,
                                        HC, SC * CH, HC * SC * CH, nsuper, 3072);

    k_dip<<<1, 1024, DIP_DYN>>>(N, nchunk, nsuper, nhyper, (float*)d_out);
}